// round 2
// baseline (speedup 1.0000x reference)
#include <cuda_runtime.h>
#include <cuda_fp16.h>
#include <cuda_bf16.h>
#include <math.h>

// Problem constants
#define NN 4096
#define NF 512
#define NH 8
#define NC 64
#define HC 512           // NH*NC
#define TC 72            // X-tilde cols: 64 feat + 1 ones + 7 pad

// -------- scratch (device globals; no allocation allowed) --------
__device__ float  g_xl[(size_t)NN * HC];                 // x@W+b, fp32
__device__ float  g_al[(size_t)NN * NH];                 // alpha_l
__device__ float  g_ar[(size_t)NN * NH];                 // alpha_r
__device__ float  g_rmax[NH];
__device__ float  g_rmin[NH];
__device__ __half g_X[(size_t)NH * NN * TC];             // [h][j][72] fp16
__device__ __half g_P[(size_t)NH * NN * NN];             // [h][i][j] fp16, 268MB

// =================================================================
// K1: x_l = x @ W + b   (4096x512x512, fp32 tiled)
// =================================================================
#define BM 64
#define BN 64
#define BK 16
__global__ void __launch_bounds__(256) k_gemm_xl(const float* __restrict__ X,
                                                 const float* __restrict__ W,
                                                 const float* __restrict__ B) {
    __shared__ float As[BK][BM + 4];
    __shared__ float Bs[BK][BN + 4];
    int tid = threadIdx.x;
    int tx = tid & 15, ty = tid >> 4;
    int n0 = blockIdx.x * BN;
    int m0 = blockIdx.y * BM;
    float acc[4][4] = {};
    for (int k0 = 0; k0 < NF; k0 += BK) {
        // A: 64 rows x 16 k
        {
            int m = tid >> 2, kq = (tid & 3) * 4;
            float4 v = *(const float4*)&X[(size_t)(m0 + m) * NF + k0 + kq];
            As[kq + 0][m] = v.x; As[kq + 1][m] = v.y;
            As[kq + 2][m] = v.z; As[kq + 3][m] = v.w;
        }
        // B(W): 16 k x 64 cols
        {
            int r = tid >> 4, c = (tid & 15) * 4;
            float4 v = *(const float4*)&W[(size_t)(k0 + r) * HC + n0 + c];
            Bs[r][c + 0] = v.x; Bs[r][c + 1] = v.y;
            Bs[r][c + 2] = v.z; Bs[r][c + 3] = v.w;
        }
        __syncthreads();
#pragma unroll
        for (int kk = 0; kk < BK; kk++) {
            float a[4], bb[4];
#pragma unroll
            for (int i = 0; i < 4; i++) a[i] = As[kk][ty * 4 + i];
#pragma unroll
            for (int j = 0; j < 4; j++) bb[j] = Bs[kk][tx * 4 + j];
#pragma unroll
            for (int i = 0; i < 4; i++)
#pragma unroll
                for (int j = 0; j < 4; j++) acc[i][j] = fmaf(a[i], bb[j], acc[i][j]);
        }
        __syncthreads();
    }
#pragma unroll
    for (int i = 0; i < 4; i++)
#pragma unroll
        for (int j = 0; j < 4; j++) {
            int col = n0 + tx * 4 + j;
            g_xl[(size_t)(m0 + ty * 4 + i) * HC + col] = acc[i][j] + B[col];
        }
}

// =================================================================
// K2: alphas + build X-tilde fp16  (one block per node, warp per head)
// =================================================================
__global__ void __launch_bounds__(256) k_alpha_x(const float* __restrict__ att_l,
                                                 const float* __restrict__ att_r) {
    int n = blockIdx.x;
    int w = threadIdx.x >> 5;      // head
    int lane = threadIdx.x & 31;
    const float* row = g_xl + (size_t)n * HC + w * NC;
    float x0 = row[lane], x1 = row[lane + 32];
    float al0 = att_l[w * NC + lane], al1 = att_l[w * NC + lane + 32];
    float ar0 = att_r[w * NC + lane], ar1 = att_r[w * NC + lane + 32];
    float sl = fmaf(x0, al0, x1 * al1);
    float sr = fmaf(x0, ar0, x1 * ar1);
#pragma unroll
    for (int o = 16; o; o >>= 1) {
        sl += __shfl_xor_sync(0xFFFFFFFFu, sl, o);
        sr += __shfl_xor_sync(0xFFFFFFFFu, sr, o);
    }
    if (lane == 0) { g_al[n * NH + w] = sl; g_ar[n * NH + w] = sr; }
    __half* xr = g_X + ((size_t)w * NN + n) * TC;
    xr[lane]      = __float2half(x0);
    xr[lane + 32] = __float2half(x1);
    if (lane < 8) xr[64 + lane] = (lane == 0) ? __float2half(1.0f) : __float2half(0.0f);
}

// =================================================================
// K3: per-head global max/min of alpha_r (single block, 512 thr)
// =================================================================
__global__ void __launch_bounds__(512) k_rstat() {
    int tid = threadIdx.x;
    int h = tid & 7, grp = tid >> 3;    // 64 groups per head
    float mx = -3.0e38f, mn = 3.0e38f;
    for (int j = grp; j < NN; j += 64) {
        float v = g_ar[j * NH + h];
        mx = fmaxf(mx, v);
        mn = fminf(mn, v);
    }
    __shared__ float smx[512], smn[512];
    smx[tid] = mx; smn[tid] = mn;
    __syncthreads();
    for (int s = 256; s >= 8; s >>= 1) {
        if (tid < s) {
            smx[tid] = fmaxf(smx[tid], smx[tid + s]);
            smn[tid] = fminf(smn[tid], smn[tid + s]);
        }
        __syncthreads();
    }
    if (tid < 8) { g_rmax[tid] = smx[tid]; g_rmin[tid] = smn[tid]; }
}

// =================================================================
// K4: materialize P[h][i][j] = adj ? exp(a_l[i,h]*a_r[j,h] - m[i,h]) : 0
//     exponents <= 0 by construction -> fp16-safe
// =================================================================
__global__ void __launch_bounds__(256) k_pmat(const int* __restrict__ adj) {
    int i = blockIdx.y;
    int j = blockIdx.x * 256 + threadIdx.x;
    float a[NH], m[NH];
#pragma unroll
    for (int h = 0; h < NH; h++) {
        float av = g_al[i * NH + h];
        a[h] = av;
        m[h] = (av >= 0.0f) ? av * g_rmax[h] : av * g_rmin[h];
    }
    int e = __ldg(&adj[(size_t)i * NN + j]);
    float4 r0 = *(const float4*)&g_ar[(size_t)j * NH];
    float4 r1 = *(const float4*)&g_ar[(size_t)j * NH + 4];
    float r[NH] = {r0.x, r0.y, r0.z, r0.w, r1.x, r1.y, r1.z, r1.w};
    size_t base = (size_t)i * NN + j;
#pragma unroll
    for (int h = 0; h < NH; h++) {
        float w = (e > 0) ? __expf(fmaf(a[h], r[h], -m[h])) : 0.0f;
        g_P[((size_t)h << 24) + base] = __float2half(w);
    }
}

// =================================================================
// K5: per head: C[4096x72] = P_h[4096x4096] @ X_h[4096x72]  (fp16 HMMA)
//     epilogue: out[i, h*64+c] = relu(C[i,c] / C[i,64])
// =================================================================
#define MT 128
#define KT 64
// smem: sA uint[128][36] (k-pairs, padded) | sB uint[72][36] (B^T, padded)
// epilogue reuses as Cs float[128][73]
__global__ void __launch_bounds__(128) k_agg(float* __restrict__ out) {
    __shared__ __align__(16) unsigned char smem_raw[128 * 73 * 4 + 64];
    unsigned int* sA  = (unsigned int*)smem_raw;                  // [128][36]
    unsigned int* sBu = (unsigned int*)(smem_raw + 128 * 36 * 4); // [72][36]
    __half*       sBh = (__half*)sBu;                             // [72][72 halfs]
    float*        Cs  = (float*)smem_raw;                         // [128][73]

    int h = blockIdx.y;
    int i0 = blockIdx.x * MT;
    int tid = threadIdx.x;
    int warp = tid >> 5, lane = tid & 31;
    int gid = lane >> 2, tig = lane & 3;

    const __half* Ph = g_P + ((size_t)h << 24);
    const __half* Bh = g_X + (size_t)h * NN * TC;

    float acc[2][9][4];
#pragma unroll
    for (int mi = 0; mi < 2; mi++)
#pragma unroll
        for (int ni = 0; ni < 9; ni++)
#pragma unroll
            for (int q = 0; q < 4; q++) acc[mi][ni][q] = 0.0f;

    for (int k0 = 0; k0 < NN; k0 += KT) {
        // ---- load A tile: 128 rows x 64 halfs (32 uints/row) ----
        const unsigned int* gA = (const unsigned int*)(Ph + (size_t)i0 * NN + k0);
#pragma unroll
        for (int q = 0; q < 32; q++) {
            int idx = q * 128 + tid;
            int r = idx >> 5, c = idx & 31;
            sA[r * 36 + c] = gA[(size_t)r * (NN / 2) + c];
        }
        // ---- load B tile 64x72 halfs, transpose into sBh[n][k] ----
        const unsigned int* gB = (const unsigned int*)(Bh + (size_t)k0 * TC);
#pragma unroll
        for (int q = 0; q < 18; q++) {
            int idx = q * 128 + tid;            // 0..2303
            int r = idx / 36, c = idx - r * 36; // j-row, half-pair
            unsigned int v = gB[r * 36 + c];
            sBh[(2 * c) * TC + r]     = __ushort_as_half((unsigned short)(v & 0xFFFF));
            sBh[(2 * c + 1) * TC + r] = __ushort_as_half((unsigned short)(v >> 16));
        }
        __syncthreads();

        int mbase = warp * 32;
#pragma unroll
        for (int ki = 0; ki < 4; ki++) {
            unsigned int afr[2][4];
#pragma unroll
            for (int mi = 0; mi < 2; mi++) {
                int r0 = mbase + mi * 16 + gid;
                afr[mi][0] = sA[(r0)     * 36 + ki * 8 + tig];
                afr[mi][1] = sA[(r0 + 8) * 36 + ki * 8 + tig];
                afr[mi][2] = sA[(r0)     * 36 + ki * 8 + tig + 4];
                afr[mi][3] = sA[(r0 + 8) * 36 + ki * 8 + tig + 4];
            }
#pragma unroll
            for (int ni = 0; ni < 9; ni++) {
                int n = ni * 8 + gid;
                unsigned int b0 = sBu[n * 36 + ki * 8 + tig];
                unsigned int b1 = sBu[n * 36 + ki * 8 + tig + 4];
#pragma unroll
                for (int mi = 0; mi < 2; mi++) {
                    asm volatile(
                        "mma.sync.aligned.m16n8k16.row.col.f32.f16.f16.f32 "
                        "{%0,%1,%2,%3}, {%4,%5,%6,%7}, {%8,%9}, {%0,%1,%2,%3};\n"
                        : "+f"(acc[mi][ni][0]), "+f"(acc[mi][ni][1]),
                          "+f"(acc[mi][ni][2]), "+f"(acc[mi][ni][3])
                        : "r"(afr[mi][0]), "r"(afr[mi][1]),
                          "r"(afr[mi][2]), "r"(afr[mi][3]),
                          "r"(b0), "r"(b1));
                }
            }
        }
        __syncthreads();
    }

    // ---- epilogue: dump accumulators to smem, normalize, relu, store ----
#pragma unroll
    for (int mi = 0; mi < 2; mi++)
#pragma unroll
        for (int ni = 0; ni < 9; ni++) {
            int r0 = warp * 32 + mi * 16 + gid;
            int cc = ni * 8 + tig * 2;
            Cs[(r0)     * 73 + cc]     = acc[mi][ni][0];
            Cs[(r0)     * 73 + cc + 1] = acc[mi][ni][1];
            Cs[(r0 + 8) * 73 + cc]     = acc[mi][ni][2];
            Cs[(r0 + 8) * 73 + cc + 1] = acc[mi][ni][3];
        }
    __syncthreads();
#pragma unroll
    for (int q = 0; q < 64; q++) {
        int idx = q * 128 + tid;
        int r = idx >> 6, c = idx & 63;
        float z = Cs[r * 73 + 64];
        float v = Cs[r * 73 + c];
        v = (z > 0.0f) ? (v / z) : 0.0f;
        out[(size_t)(i0 + r) * HC + h * NC + c] = fmaxf(v, 0.0f);
    }
}

// =================================================================
extern "C" void kernel_launch(void* const* d_in, const int* in_sizes, int n_in,
                              void* d_out, int out_size) {
    const float* x     = (const float*)d_in[0];
    const int*   adj   = (const int*)d_in[1];
    const float* W     = (const float*)d_in[2];
    const float* b     = (const float*)d_in[3];
    const float* att_l = (const float*)d_in[4];
    const float* att_r = (const float*)d_in[5];
    float* out = (float*)d_out;

    k_gemm_xl<<<dim3(HC / BN, NN / BM), 256>>>(x, W, b);
    k_alpha_x<<<NN, 256>>>(att_l, att_r);
    k_rstat<<<1, 512>>>();
    k_pmat<<<dim3(NN / 256, NN), 256>>>(adj);
    k_agg<<<dim3(NN / MT, NH), 128>>>(out);
}